// round 6
// baseline (speedup 1.0000x reference)
#include <cuda_runtime.h>
#include <cuda_fp16.h>
#include <math.h>
#include <stdint.h>

#define LL 16384
#define DD 1024
#define AA 1024

// ---------------- device scratch (static: allocation-free) ----------------
__device__ __half g_hh[LL * DD];   // h split hi (32 MB, fp16)
__device__ __half g_hl[LL * DD];   // h split lo (32 MB, fp16)
__device__ __half g_w16[AA * DD];  // W1 fp16 (2 MB)
__device__ float g_c[AA];
__device__ float g_beta[LL];
__device__ float g_red[2];         // [0]=max, [1]=sum(exp)

// ---------------- PTX helpers (arch-neutral: sm_80+ features only) --------
__device__ __forceinline__ uint32_t smem_u32(const void* p){
    uint32_t a;
    asm("{ .reg .u64 t; cvta.to.shared.u64 t, %1; cvt.u32.u64 %0, t; }" : "=r"(a) : "l"(p));
    return a;
}
__device__ __forceinline__ void cp16(uint32_t dst, const void* src){
    asm volatile("cp.async.cg.shared.global [%0], [%1], 16;" :: "r"(dst), "l"(src) : "memory");
}
__device__ __forceinline__ void cp_commit(){
    asm volatile("cp.async.commit_group;" ::: "memory");
}
template<int N>
__device__ __forceinline__ void cp_wait(){
    asm volatile("cp.async.wait_group %0;" :: "n"(N) : "memory");
}
__device__ __forceinline__ void ldm4(uint32_t* r, uint32_t addr){
    asm volatile("ldmatrix.sync.aligned.m8n8.x4.shared.b16 {%0,%1,%2,%3}, [%4];"
        : "=r"(r[0]), "=r"(r[1]), "=r"(r[2]), "=r"(r[3]) : "r"(addr));
}
__device__ __forceinline__ void mma16816(float* d, const uint32_t* a,
                                         uint32_t b0, uint32_t b1){
    asm volatile(
        "mma.sync.aligned.m16n8k16.row.col.f32.f16.f16.f32 "
        "{%0,%1,%2,%3}, {%4,%5,%6,%7}, {%8,%9}, {%0,%1,%2,%3};"
        : "+f"(d[0]), "+f"(d[1]), "+f"(d[2]), "+f"(d[3])
        : "r"(a[0]), "r"(a[1]), "r"(a[2]), "r"(a[3]), "r"(b0), "r"(b1));
}

__device__ __forceinline__ float fast_tanh(float x){
    float e = __expf(-2.0f * fabsf(x));
    float t = __fdividef(1.0f - e, 1.0f + e);
    return copysignf(t, x);
}

// ---------------- conversion kernels ----------------
// h -> fp16 hi/lo split (exact to ~2^-23)
__global__ void conv_h_kernel(const float* __restrict__ h){
    int idx = blockIdx.x * 256 + threadIdx.x;            // 4,194,304 float4s
    float4 v = ((const float4*)h)[idx];
    union { __half b[4]; uint2 u; } H, L;
    H.b[0] = __float2half(v.x); L.b[0] = __float2half(v.x - __half2float(H.b[0]));
    H.b[1] = __float2half(v.y); L.b[1] = __float2half(v.y - __half2float(H.b[1]));
    H.b[2] = __float2half(v.z); L.b[2] = __float2half(v.z - __half2float(H.b[2]));
    H.b[3] = __float2half(v.w); L.b[3] = __float2half(v.w - __half2float(H.b[3]));
    ((uint2*)g_hh)[idx] = H.u;
    ((uint2*)g_hl)[idx] = L.u;
}

// W1 (cols [0,1024) of W_att) -> single fp16; also zero beta accumulators
__global__ void conv_w_kernel(const float* __restrict__ W){
    int idx = blockIdx.x * 256 + threadIdx.x;            // 262,144 float4s
    if (idx < LL) g_beta[idx] = 0.f;
    int a = idx >> 8, kg = idx & 255;
    float4 v = ((const float4*)(W + (size_t)a * 2048))[kg];
    union { __half b[4]; uint2 u; } H;
    H.b[0] = __float2half(v.x);
    H.b[1] = __float2half(v.y);
    H.b[2] = __float2half(v.z);
    H.b[3] = __float2half(v.w);
    ((uint2*)g_w16)[idx] = H.u;
}

// ---------------- kernel A: c = W2 @ h_t + b ----------------
__global__ void compute_c_kernel(const float* __restrict__ ht,
                                 const float* __restrict__ W,
                                 const float* __restrict__ b){
    int w = threadIdx.x >> 5, lane = threadIdx.x & 31;
    int a = blockIdx.x * 8 + w;
    const float* Wr = W + (size_t)a * 2048 + 1024;
    float s = 0.f;
    #pragma unroll 4
    for (int k = lane; k < 1024; k += 32) s += Wr[k] * ht[k];
    #pragma unroll
    for (int o = 16; o; o >>= 1) s += __shfl_xor_sync(0xffffffffu, s, o);
    if (lane == 0) g_c[a] = s + b[a];
}

// ---------------- kernel B: fp16 2-product mma.sync GEMM + fused epilogue -----
// y = A_hi*W + A_lo*W  (A split fp16, W single fp16)
// CTA tile 128x128, 256 threads (8 warps, 4m x 2n). 3-stage cp.async pipeline,
// K=32 per stage (2 k-halves per barrier), 2 CTAs/SM.
// HMMA ordering: all aH products, then all aL products (RAW distance 16).
// smem row stride 40 halves (80B) -> conflict-free ldmatrix.
// Stage layout (bytes): [Ah 10240][Al 10240][W 10240] = 30720, x3 stages.
#define RSTRIDE  40
#define BUFB     10240
#define STAGEB   30720
#define NSTAGE   3
#define KSTAGES  32            // 1024 / 32
#define DYN_SMEM (NSTAGE * STAGEB)

__device__ __forceinline__ void load_stage(uint32_t sb, int slot, int m_base, int n_base,
                                           int k0, int tid){
    uint32_t st  = sb + (uint32_t)slot * STAGEB;
    int row = tid >> 1;                  // 0..127
    int c8  = (tid & 1) * 8;             // 0 or 8
    uint32_t d0 = (uint32_t)((row * RSTRIDE + c8) * 2);
    uint32_t d1 = (uint32_t)((row * RSTRIDE + c8 + 16) * 2);
    size_t ga = (size_t)(m_base + row) * DD + k0 + c8;
    size_t gb = (size_t)(n_base + row) * DD + k0 + c8;
    cp16(st + d0,            g_hh  + ga);
    cp16(st + d1,            g_hh  + ga + 16);
    cp16(st + BUFB + d0,     g_hl  + ga);
    cp16(st + BUFB + d1,     g_hl  + ga + 16);
    cp16(st + 2 * BUFB + d0, g_w16 + gb);
    cp16(st + 2 * BUFB + d1, g_w16 + gb + 16);
    cp_commit();
}

__global__ __launch_bounds__(256, 2)
void beta_mma_kernel(const float* __restrict__ u){
    extern __shared__ char dyn_sm[];
    __shared__ float cs[128], us[128];

    const int tid  = threadIdx.x;
    const int lane = tid & 31;
    const int wid  = tid >> 5;
    const int warp_m = wid & 3;        // 4 warps along m (32 rows each)
    const int warp_n = wid >> 2;       // 2 warps along n (64 cols each)
    const int m_base = blockIdx.x * 128;
    const int n_base = blockIdx.y * 128;
    const uint32_t sb = smem_u32(dyn_sm);

    if (tid < 128){ cs[tid] = g_c[n_base + tid]; us[tid] = u[n_base + tid]; }

    float acc[2][8][4];
    #pragma unroll
    for (int im = 0; im < 2; ++im)
        #pragma unroll
        for (int j = 0; j < 8; ++j)
            #pragma unroll
            for (int p = 0; p < 4; ++p) acc[im][j][p] = 0.f;

    load_stage(sb, 0, m_base, n_base, 0,  tid);
    load_stage(sb, 1, m_base, n_base, 32, tid);

    const int lr = lane & 15;
    const int lq = ((lane >> 4) & 1) * 8;

    int s = 0, sl = 2;                   // consume slot, next-fill slot
    for (int kt = 0; kt < KSTAGES; ++kt){
        cp_wait<1>();
        __syncthreads();

        if (kt + 2 < KSTAGES)
            load_stage(sb, sl, m_base, n_base, (kt + 2) * 32, tid);
        else
            cp_commit();   // keep wait_group bookkeeping uniform

        uint32_t st = sb + (uint32_t)s * STAGEB;
        #pragma unroll
        for (int half = 0; half < 2; ++half){
            const uint32_t col = lq + half * 16;
            uint32_t aH[2][4], aL[2][4], bW[4][4];
            #pragma unroll
            for (int im = 0; im < 2; ++im){
                uint32_t off = (uint32_t)(((warp_m * 32 + im * 16 + lr) * RSTRIDE + col) * 2);
                ldm4(aH[im], st + off);
                ldm4(aL[im], st + BUFB + off);
            }
            #pragma unroll
            for (int t = 0; t < 4; ++t){
                uint32_t off = (uint32_t)(((warp_n * 64 + t * 16 + lr) * RSTRIDE + col) * 2);
                ldm4(bW[t], st + 2 * BUFB + off);
            }
            // all aH products first, then all aL products: RAW distance 16
            #pragma unroll
            for (int im = 0; im < 2; ++im)
                #pragma unroll
                for (int i8 = 0; i8 < 8; ++i8){
                    const int t = i8 >> 1, hf = i8 & 1;
                    mma16816(acc[im][i8], aH[im], bW[t][hf], bW[t][hf + 2]);
                }
            #pragma unroll
            for (int im = 0; im < 2; ++im)
                #pragma unroll
                for (int i8 = 0; i8 < 8; ++i8){
                    const int t = i8 >> 1, hf = i8 & 1;
                    mma16816(acc[im][i8], aL[im], bW[t][hf], bW[t][hf + 2]);
                }
        }

        s  = (s  == NSTAGE - 1) ? 0 : s + 1;
        sl = (sl == NSTAGE - 1) ? 0 : sl + 1;
    }

    // epilogue: tanh(y + c) * u, reduce over n, atomic into g_beta
    #pragma unroll
    for (int im = 0; im < 2; ++im){
        #pragma unroll
        for (int rh = 0; rh < 2; ++rh){
            float p = 0.f;
            #pragma unroll
            for (int i8 = 0; i8 < 8; ++i8){
                int n = warp_n * 64 + i8 * 8 + 2 * (lane & 3);
                float v0 = acc[im][i8][rh * 2 + 0];
                float v1 = acc[im][i8][rh * 2 + 1];
                p += fast_tanh(v0 + cs[n])     * us[n];
                p += fast_tanh(v1 + cs[n + 1]) * us[n + 1];
            }
            p += __shfl_xor_sync(0xffffffffu, p, 1);
            p += __shfl_xor_sync(0xffffffffu, p, 2);
            if ((lane & 3) == 0){
                int row = m_base + warp_m * 32 + im * 16 + rh * 8 + (lane >> 2);
                atomicAdd(&g_beta[row], p);
            }
        }
    }
}

// ---------------- kernel C: softmax reductions + zero output ----------------
__global__ void softmax_kernel(float* __restrict__ out){
    __shared__ float red[32];
    const int tid = threadIdx.x;   // 1024 threads
    float mx = -3.0e38f;
    for (int i = tid; i < LL; i += 1024) mx = fmaxf(mx, g_beta[i]);
    #pragma unroll
    for (int o = 16; o; o >>= 1) mx = fmaxf(mx, __shfl_xor_sync(0xffffffffu, mx, o));
    if ((tid & 31) == 0) red[tid >> 5] = mx;
    __syncthreads();
    if (tid < 32){
        float v = red[tid];
        #pragma unroll
        for (int o = 16; o; o >>= 1) v = fmaxf(v, __shfl_xor_sync(0xffffffffu, v, o));
        if (tid == 0) red[0] = v;
    }
    __syncthreads();
    mx = red[0];
    __syncthreads();

    float s = 0.f;
    for (int i = tid; i < LL; i += 1024) s += __expf(g_beta[i] - mx);
    #pragma unroll
    for (int o = 16; o; o >>= 1) s += __shfl_xor_sync(0xffffffffu, s, o);
    if ((tid & 31) == 0) red[tid >> 5] = s;
    __syncthreads();
    if (tid < 32){
        float v = red[tid];
        #pragma unroll
        for (int o = 16; o; o >>= 1) v += __shfl_xor_sync(0xffffffffu, v, o);
        if (tid == 0){ g_red[0] = mx; g_red[1] = v; }
    }
    out[tid] = 0.f;
}

// ---------------- kernel D: s[d] = sum_i alpha_i * h[i][d] ----------------
__global__ __launch_bounds__(256)
void wsum_kernel(const float* __restrict__ h, float* __restrict__ out){
    __shared__ float wsm[128];
    const int tid = threadIdx.x;
    const int i0 = blockIdx.x * 128;     // 128 blocks x 128 rows
    if (tid < 128)
        wsm[tid] = __expf(g_beta[i0 + tid] - g_red[0]) * (1.0f / g_red[1]);
    __syncthreads();

    const float4* hp = (const float4*)(h + (size_t)i0 * 1024) + tid;  // col group tid
    float4 acc = make_float4(0.f, 0.f, 0.f, 0.f);
    #pragma unroll 4
    for (int i = 0; i < 128; ++i){
        float w = wsm[i];
        float4 v = hp[(size_t)i * 256];
        acc.x += w * v.x; acc.y += w * v.y; acc.z += w * v.z; acc.w += w * v.w;
    }
    atomicAdd(&out[tid * 4 + 0], acc.x);
    atomicAdd(&out[tid * 4 + 1], acc.y);
    atomicAdd(&out[tid * 4 + 2], acc.z);
    atomicAdd(&out[tid * 4 + 3], acc.w);
}

// ---------------- launch ----------------
extern "C" void kernel_launch(void* const* d_in, const int* in_sizes, int n_in,
                              void* d_out, int out_size){
    const float* h_i   = (const float*)d_in[0];
    const float* h_t   = (const float*)d_in[1];
    const float* W_att = (const float*)d_in[2];
    const float* b_att = (const float*)d_in[3];
    const float* u     = (const float*)d_in[4];
    float* out = (float*)d_out;

    cudaFuncSetAttribute(beta_mma_kernel,
                         cudaFuncAttributeMaxDynamicSharedMemorySize, DYN_SMEM);

    conv_h_kernel<<<16384, 256>>>(h_i);
    conv_w_kernel<<<1024, 256>>>(W_att);
    compute_c_kernel<<<128, 256>>>(h_t, W_att, b_att);
    beta_mma_kernel<<<dim3(128, 8), 256, DYN_SMEM>>>(u);
    softmax_kernel<<<1, 1024>>>(out);
    wsum_kernel<<<128, 256>>>(h_i, out);
}

// round 7
// speedup vs baseline: 1.5355x; 1.5355x over previous
#include <cuda_runtime.h>
#include <cuda_fp16.h>
#include <math.h>
#include <stdint.h>

#define LL 16384
#define DD 1024
#define AA 1024

// ---------------- device scratch (static: allocation-free) ----------------
__device__ __half g_h16[LL * DD];  // h fp16 (32 MB)
__device__ __half g_w16[AA * DD];  // W1 fp16 (2 MB)
__device__ float g_c[AA];
__device__ float g_beta[LL];
__device__ float g_red[2];         // [0]=max, [1]=sum(exp)

// ---------------- PTX helpers (arch-neutral: sm_80+ features only) --------
__device__ __forceinline__ uint32_t smem_u32(const void* p){
    uint32_t a;
    asm("{ .reg .u64 t; cvta.to.shared.u64 t, %1; cvt.u32.u64 %0, t; }" : "=r"(a) : "l"(p));
    return a;
}
__device__ __forceinline__ void cp16(uint32_t dst, const void* src){
    asm volatile("cp.async.cg.shared.global [%0], [%1], 16;" :: "r"(dst), "l"(src) : "memory");
}
__device__ __forceinline__ void cp_commit(){
    asm volatile("cp.async.commit_group;" ::: "memory");
}
template<int N>
__device__ __forceinline__ void cp_wait(){
    asm volatile("cp.async.wait_group %0;" :: "n"(N) : "memory");
}
__device__ __forceinline__ void ldm4(uint32_t* r, uint32_t addr){
    asm volatile("ldmatrix.sync.aligned.m8n8.x4.shared.b16 {%0,%1,%2,%3}, [%4];"
        : "=r"(r[0]), "=r"(r[1]), "=r"(r[2]), "=r"(r[3]) : "r"(addr));
}
__device__ __forceinline__ void mma16816(float* d, const uint32_t* a,
                                         uint32_t b0, uint32_t b1){
    asm volatile(
        "mma.sync.aligned.m16n8k16.row.col.f32.f16.f16.f32 "
        "{%0,%1,%2,%3}, {%4,%5,%6,%7}, {%8,%9}, {%0,%1,%2,%3};"
        : "+f"(d[0]), "+f"(d[1]), "+f"(d[2]), "+f"(d[3])
        : "r"(a[0]), "r"(a[1]), "r"(a[2]), "r"(a[3]), "r"(b0), "r"(b1));
}

__device__ __forceinline__ float fast_tanh(float x){
    float e = __expf(-2.0f * fabsf(x));
    float t = __fdividef(1.0f - e, 1.0f + e);
    return copysignf(t, x);
}

// ---------------- conversion kernels ----------------
// h -> fp16
__global__ void conv_h_kernel(const float* __restrict__ h){
    int idx = blockIdx.x * 256 + threadIdx.x;            // 4,194,304 float4s
    float4 v = ((const float4*)h)[idx];
    union { __half b[4]; uint2 u; } H;
    H.b[0] = __float2half(v.x);
    H.b[1] = __float2half(v.y);
    H.b[2] = __float2half(v.z);
    H.b[3] = __float2half(v.w);
    ((uint2*)g_h16)[idx] = H.u;
}

// W1 (cols [0,1024) of W_att) -> fp16; also zero beta accumulators
__global__ void conv_w_kernel(const float* __restrict__ W){
    int idx = blockIdx.x * 256 + threadIdx.x;            // 262,144 float4s
    if (idx < LL) g_beta[idx] = 0.f;
    int a = idx >> 8, kg = idx & 255;
    float4 v = ((const float4*)(W + (size_t)a * 2048))[kg];
    union { __half b[4]; uint2 u; } H;
    H.b[0] = __float2half(v.x);
    H.b[1] = __float2half(v.y);
    H.b[2] = __float2half(v.z);
    H.b[3] = __float2half(v.w);
    ((uint2*)g_w16)[idx] = H.u;
}

// ---------------- kernel A: c = W2 @ h_t + b ----------------
__global__ void compute_c_kernel(const float* __restrict__ ht,
                                 const float* __restrict__ W,
                                 const float* __restrict__ b){
    int w = threadIdx.x >> 5, lane = threadIdx.x & 31;
    int a = blockIdx.x * 8 + w;
    const float* Wr = W + (size_t)a * 2048 + 1024;
    float s = 0.f;
    #pragma unroll 4
    for (int k = lane; k < 1024; k += 32) s += Wr[k] * ht[k];
    #pragma unroll
    for (int o = 16; o; o >>= 1) s += __shfl_xor_sync(0xffffffffu, s, o);
    if (lane == 0) g_c[a] = s + b[a];
}

// ---------------- kernel B: single fp16 product mma.sync GEMM --------------
// y = A16 * W16^T. CTA tile 128x128, 256 threads (8 warps, 4m x 2n),
// warp tile 32x64. K=64 per stage, 3-stage cp.async pipeline (16 barriers),
// 2 CTAs/SM. smem row stride 72 halves (144B) -> conflict-free ldmatrix.
// Stage layout (bytes): [A 18432][W 18432] = 36864, x3 stages.
#define RSTRIDE  72
#define BUFB     18432
#define STAGEB   36864
#define NSTAGE   3
#define KSTAGES  16            // 1024 / 64
#define DYN_SMEM (NSTAGE * STAGEB)

__device__ __forceinline__ void load_stage(uint32_t sb, int slot, int m_base, int n_base,
                                           int k0, int tid){
    uint32_t st  = sb + (uint32_t)slot * STAGEB;
    int row = tid >> 1;                      // 0..127
    int cb  = (tid & 1) * 32;                // col base: 0 or 32
    #pragma unroll
    for (int j = 0; j < 4; ++j){
        int col = cb + j * 8;
        uint32_t doff = (uint32_t)((row * RSTRIDE + col) * 2);
        cp16(st + doff,        g_h16 + (size_t)(m_base + row) * DD + k0 + col);
        cp16(st + BUFB + doff, g_w16 + (size_t)(n_base + row) * DD + k0 + col);
    }
    cp_commit();
}

__global__ __launch_bounds__(256, 2)
void beta_mma_kernel(const float* __restrict__ u){
    extern __shared__ char dyn_sm[];
    __shared__ float cs[128], us[128];

    const int tid  = threadIdx.x;
    const int lane = tid & 31;
    const int wid  = tid >> 5;
    const int warp_m = wid & 3;        // 4 warps along m (32 rows each)
    const int warp_n = wid >> 2;       // 2 warps along n (64 cols each)
    const int m_base = blockIdx.x * 128;
    const int n_base = blockIdx.y * 128;
    const uint32_t sb = smem_u32(dyn_sm);

    if (tid < 128){ cs[tid] = g_c[n_base + tid]; us[tid] = u[n_base + tid]; }

    float acc[2][8][4];
    #pragma unroll
    for (int im = 0; im < 2; ++im)
        #pragma unroll
        for (int j = 0; j < 8; ++j)
            #pragma unroll
            for (int p = 0; p < 4; ++p) acc[im][j][p] = 0.f;

    load_stage(sb, 0, m_base, n_base, 0,  tid);
    load_stage(sb, 1, m_base, n_base, 64, tid);

    const int lr = lane & 15;
    const int lq = ((lane >> 4) & 1) * 8;

    int s = 0, sl = 2;                   // consume slot, next-fill slot
    for (int kt = 0; kt < KSTAGES; ++kt){
        cp_wait<1>();
        __syncthreads();

        if (kt + 2 < KSTAGES)
            load_stage(sb, sl, m_base, n_base, (kt + 2) * 64, tid);
        else
            cp_commit();   // keep wait_group bookkeeping uniform

        uint32_t st = sb + (uint32_t)s * STAGEB;
        #pragma unroll
        for (int half = 0; half < 4; ++half){
            const uint32_t col = lq + half * 16;
            uint32_t aF[2][4], bW[4][4];
            #pragma unroll
            for (int im = 0; im < 2; ++im){
                uint32_t off = (uint32_t)(((warp_m * 32 + im * 16 + lr) * RSTRIDE + col) * 2);
                ldm4(aF[im], st + off);
            }
            #pragma unroll
            for (int t = 0; t < 4; ++t){
                uint32_t off = (uint32_t)(((warp_n * 64 + t * 16 + lr) * RSTRIDE + col) * 2);
                ldm4(bW[t], st + BUFB + off);
            }
            #pragma unroll
            for (int im = 0; im < 2; ++im)
                #pragma unroll
                for (int i8 = 0; i8 < 8; ++i8){
                    const int t = i8 >> 1, hf = i8 & 1;
                    mma16816(acc[im][i8], aF[im], bW[t][hf], bW[t][hf + 2]);
                }
        }

        s  = (s  == NSTAGE - 1) ? 0 : s + 1;
        sl = (sl == NSTAGE - 1) ? 0 : sl + 1;
    }

    // epilogue: tanh(y + c) * u, reduce over n, atomic into g_beta
    #pragma unroll
    for (int im = 0; im < 2; ++im){
        #pragma unroll
        for (int rh = 0; rh < 2; ++rh){
            float p = 0.f;
            #pragma unroll
            for (int i8 = 0; i8 < 8; ++i8){
                int n = warp_n * 64 + i8 * 8 + 2 * (lane & 3);
                float v0 = acc[im][i8][rh * 2 + 0];
                float v1 = acc[im][i8][rh * 2 + 1];
                p += fast_tanh(v0 + cs[n])     * us[n];
                p += fast_tanh(v1 + cs[n + 1]) * us[n + 1];
            }
            p += __shfl_xor_sync(0xffffffffu, p, 1);
            p += __shfl_xor_sync(0xffffffffu, p, 2);
            if ((lane & 3) == 0){
                int row = m_base + warp_m * 32 + im * 16 + rh * 8 + (lane >> 2);
                atomicAdd(&g_beta[row], p);
            }
        }
    }
}

// ---------------- kernel C: softmax reductions + zero output ----------------
__global__ void softmax_kernel(float* __restrict__ out){
    __shared__ float red[32];
    const int tid = threadIdx.x;   // 1024 threads
    float mx = -3.0e38f;
    for (int i = tid; i < LL; i += 1024) mx = fmaxf(mx, g_beta[i]);
    #pragma unroll
    for (int o = 16; o; o >>= 1) mx = fmaxf(mx, __shfl_xor_sync(0xffffffffu, mx, o));
    if ((tid & 31) == 0) red[tid >> 5] = mx;
    __syncthreads();
    if (tid < 32){
        float v = red[tid];
        #pragma unroll
        for (int o = 16; o; o >>= 1) v = fmaxf(v, __shfl_xor_sync(0xffffffffu, v, o));
        if (tid == 0) red[0] = v;
    }
    __syncthreads();
    mx = red[0];
    __syncthreads();

    float s = 0.f;
    for (int i = tid; i < LL; i += 1024) s += __expf(g_beta[i] - mx);
    #pragma unroll
    for (int o = 16; o; o >>= 1) s += __shfl_xor_sync(0xffffffffu, s, o);
    if ((tid & 31) == 0) red[tid >> 5] = s;
    __syncthreads();
    if (tid < 32){
        float v = red[tid];
        #pragma unroll
        for (int o = 16; o; o >>= 1) v += __shfl_xor_sync(0xffffffffu, v, o);
        if (tid == 0){ g_red[0] = mx; g_red[1] = v; }
    }
    out[tid] = 0.f;
}

// ---------------- kernel D: s[d] = sum_i alpha_i * h[i][d] ----------------
__global__ __launch_bounds__(256)
void wsum_kernel(const float* __restrict__ h, float* __restrict__ out){
    __shared__ float wsm[128];
    const int tid = threadIdx.x;
    const int i0 = blockIdx.x * 128;     // 128 blocks x 128 rows
    if (tid < 128)
        wsm[tid] = __expf(g_beta[i0 + tid] - g_red[0]) * (1.0f / g_red[1]);
    __syncthreads();

    const float4* hp = (const float4*)(h + (size_t)i0 * 1024) + tid;  // col group tid
    float4 acc = make_float4(0.f, 0.f, 0.f, 0.f);
    #pragma unroll 4
    for (int i = 0; i < 128; ++i){
        float w = wsm[i];
        float4 v = hp[(size_t)i * 256];
        acc.x += w * v.x; acc.y += w * v.y; acc.z += w * v.z; acc.w += w * v.w;
    }
    atomicAdd(&out[tid * 4 + 0], acc.x);
    atomicAdd(&out[tid * 4 + 1], acc.y);
    atomicAdd(&out[tid * 4 + 2], acc.z);
    atomicAdd(&out[tid * 4 + 3], acc.w);
}

// ---------------- launch ----------------
extern "C" void kernel_launch(void* const* d_in, const int* in_sizes, int n_in,
                              void* d_out, int out_size){
    const float* h_i   = (const float*)d_in[0];
    const float* h_t   = (const float*)d_in[1];
    const float* W_att = (const float*)d_in[2];
    const float* b_att = (const float*)d_in[3];
    const float* u     = (const float*)d_in[4];
    float* out = (float*)d_out;

    cudaFuncSetAttribute(beta_mma_kernel,
                         cudaFuncAttributeMaxDynamicSharedMemorySize, DYN_SMEM);

    conv_h_kernel<<<16384, 256>>>(h_i);
    conv_w_kernel<<<1024, 256>>>(W_att);
    compute_c_kernel<<<128, 256>>>(h_t, W_att, b_att);
    beta_mma_kernel<<<dim3(128, 8), 256, DYN_SMEM>>>(u);
    softmax_kernel<<<1, 1024>>>(out);
    wsum_kernel<<<128, 256>>>(h_i, out);
}